// round 4
// baseline (speedup 1.0000x reference)
#include <cuda_runtime.h>
#include <cstddef>

// Problem constants (fixed by the dataset)
#define NN 50000
#define EE 800000
#define HH 64      // hidden
#define DC 128     // node in channels
#define EC 16      // edge in channels
#define LL 3
#define EPS_MSG 1e-7f
#define LN_EPS 1e-5f

// ---------------- device scratch (no cudaMalloc allowed) ----------------
__device__ float g_pe[(size_t)EE * EC];     // CSR-permuted edge_attr, 51.2 MB
__device__ float g_h[(size_t)NN * HH];      // node state
__device__ float g_z[(size_t)NN * HH];      // pre-normed layer input
__device__ float g_agg[(size_t)NN * HH];    // conv output (agg + root)
__device__ float g_t1[(size_t)NN * 2 * HH]; // MLP hidden
__device__ int   g_deg[NN];
__device__ int   g_rowptr[NN + 1];
__device__ int   g_cursor[NN];
__device__ int   g_psrc[EE];

// ---------------- packed f32x2 FMA helpers ----------------
__device__ __forceinline__ unsigned long long pk2(float x, float y) {
    unsigned long long r;
    asm("mov.b64 %0, {%1,%2};" : "=l"(r) : "f"(x), "f"(y));
    return r;
}
__device__ __forceinline__ float2 upk2(unsigned long long v) {
    float2 r;
    asm("mov.b64 {%0,%1}, %2;" : "=f"(r.x), "=f"(r.y) : "l"(v));
    return r;
}
// c += a * b (a splatted across the pair)
__device__ __forceinline__ float2 ffma2(float a, float2 b, float2 c) {
    unsigned long long ra = pk2(a, a);
    unsigned long long rb = pk2(b.x, b.y);
    unsigned long long rc = pk2(c.x, c.y);
    asm("fma.rn.f32x2 %0, %1, %2, %0;" : "+l"(rc) : "l"(ra), "l"(rb));
    return upk2(rc);
}

// ---------------- CSR build: histogram / scan / scatter+permute ---------------
__global__ void hist_kernel(const int* __restrict__ dst, int* __restrict__ deg) {
    int e = blockIdx.x * blockDim.x + threadIdx.x;
    if (e < EE) atomicAdd(&deg[dst[e]], 1);
}

__global__ void scan_kernel(const int* __restrict__ deg, int* __restrict__ rowptr,
                            int* __restrict__ cursor) {
    __shared__ int sh[1024];
    const int tid = threadIdx.x;
    const int CH = (NN + 1023) / 1024;
    const int base = tid * CH;
    int s = 0;
    for (int i = 0; i < CH; i++) {
        int j = base + i;
        if (j < NN) s += deg[j];
    }
    sh[tid] = s;
    __syncthreads();
    for (int off = 1; off < 1024; off <<= 1) {
        int v = (tid >= off) ? sh[tid - off] : 0;
        __syncthreads();
        sh[tid] += v;
        __syncthreads();
    }
    int run = (tid > 0) ? sh[tid - 1] : 0;
    for (int i = 0; i < CH; i++) {
        int j = base + i;
        if (j < NN) {
            rowptr[j] = run;
            cursor[j] = run;
            run += deg[j];
        }
    }
    if (tid == 0) rowptr[NN] = sh[1023];
}

// scatter into CSR order: writes psrc AND permutes edge_attr (16 floats/edge)
__global__ __launch_bounds__(256) void scatter_kernel(const int* __restrict__ src,
                                                      const int* __restrict__ dst,
                                                      const float* __restrict__ eattr,
                                                      int* __restrict__ cursor,
                                                      int* __restrict__ psrc,
                                                      float* __restrict__ pe) {
    int e = blockIdx.x * blockDim.x + threadIdx.x;
    if (e >= EE) return;
    int idx = atomicAdd(&cursor[dst[e]], 1);
    psrc[idx] = src[e];
    const float4* in4 = reinterpret_cast<const float4*>(eattr) + (size_t)e * 4;
    float4* out4 = reinterpret_cast<float4*>(pe) + (size_t)idx * 4;
    out4[0] = in4[0];
    out4[1] = in4[1];
    out4[2] = in4[2];
    out4[3] = in4[3];
}

// ---------------- softmax aggregation with inline edge-encode -----------------
// one warp per destination node; lane l owns features {2l, 2l+1}.
// ea[e] = eattr_perm[j] @ edge_W + edge_b is recomputed here (edge_W in regs),
// trading ~1.6 GFLOP/layer of f32x2 fma for ~205 MB/layer of random HBM reads.
__global__ __launch_bounds__(256) void agg_kernel(const float* __restrict__ z,
                                                  const float* __restrict__ pe,
                                                  const int* __restrict__ psrc,
                                                  const int* __restrict__ rowptr,
                                                  const float* __restrict__ eW,
                                                  const float* __restrict__ eb,
                                                  const float* __restrict__ t_ptr,
                                                  float* __restrict__ out) {
    const int w = (blockIdx.x * blockDim.x + threadIdx.x) >> 5;
    if (w >= NN) return;
    const int lane = threadIdx.x & 31;

    float2 Wr[EC];
#pragma unroll
    for (int k = 0; k < EC; k++)
        Wr[k] = *reinterpret_cast<const float2*>(&eW[k * HH + 2 * lane]);
    const float2 bv = *reinterpret_cast<const float2*>(&eb[2 * lane]);
    const float t = *t_ptr;

    const int beg = rowptr[w], end = rowptr[w + 1];
    float2 accP = make_float2(0.f, 0.f);
    float2 accM = make_float2(0.f, 0.f);

    float a = 0.f;
    int s = 0;
    if (beg < end) {
        if (lane < EC) a = pe[(size_t)beg * EC + lane];
        s = psrc[beg];
    }
    for (int j = beg; j < end; j++) {
        float a_n = 0.f;
        int s_n = 0;
        if (j + 1 < end) {  // prefetch next edge (streaming addresses)
            if (lane < EC) a_n = pe[(size_t)(j + 1) * EC + lane];
            s_n = psrc[j + 1];
        }
        // ea for this edge's two features: split accumulation chain in half
        float2 ev0 = bv, ev1 = make_float2(0.f, 0.f);
#pragma unroll
        for (int k = 0; k < EC; k += 2) {
            ev0 = ffma2(__shfl_sync(0xffffffffu, a, k), Wr[k], ev0);
            ev1 = ffma2(__shfl_sync(0xffffffffu, a, k + 1), Wr[k + 1], ev1);
        }
        float2 zv = *reinterpret_cast<const float2*>(&z[(size_t)s * HH + 2 * lane]);
        float m0 = fmaxf(zv.x + ev0.x + ev1.x, 0.f) + EPS_MSG;
        float m1 = fmaxf(zv.y + ev0.y + ev1.y, 0.f) + EPS_MSG;
        // softmax weights without max-shift: exp args bounded (msg small, t=O(1))
        float p0 = __expf(m0 * t);
        float p1 = __expf(m1 * t);
        accP.x += p0;
        accP.y += p1;
        accM.x = fmaf(m0, p0, accM.x);
        accM.y = fmaf(m1, p1, accM.y);
        a = a_n;
        s = s_n;
    }
    float2 zd = *reinterpret_cast<const float2*>(&z[(size_t)w * HH + 2 * lane]);
    float2 o;
    o.x = (end > beg ? accM.x / accP.x : 0.f) + zd.x;
    o.y = (end > beg ? accM.y / accP.y : 0.f) + zd.y;
    *reinterpret_cast<float2*>(&out[(size_t)w * HH + 2 * lane]) = o;
}

// ---------------- GEMM NOUT=64, fused residual + dual output ------------------
// C = A[M,K] @ W[K,64] + bias (+resid). hout gets raw result; if zout!=null also
// writes zout = relu(LayerNorm64(hout; png,pnb)). 64-row tiles, warp owns 8 rows,
// lane owns features {2l,2l+1}. k stepped by 4 with float4 LDS.
template <int K>
__global__ __launch_bounds__(256) void gemm64_kernel(const float* __restrict__ A,
                                                     const float* __restrict__ W,
                                                     const float* __restrict__ bias,
                                                     const float* __restrict__ resid,
                                                     float* __restrict__ hout,
                                                     const float* __restrict__ png,
                                                     const float* __restrict__ pnb,
                                                     float* __restrict__ zout, int M) {
    extern __shared__ float sh[];
    float* sA = sh;            // 64*K
    float* sW = sh + 64 * K;   // K*64
    const int tid = threadIdx.x;
    const int m0 = blockIdx.x * 64;

    for (int idx = tid * 4; idx < 64 * K; idx += 1024) {
        int row = idx / K, col = idx % K;
        float4 v = make_float4(0.f, 0.f, 0.f, 0.f);
        if (m0 + row < M)
            v = *reinterpret_cast<const float4*>(&A[(size_t)(m0 + row) * K + col]);
        *reinterpret_cast<float4*>(&sA[idx]) = v;
    }
    for (int idx = tid * 4; idx < K * 64; idx += 1024)
        *reinterpret_cast<float4*>(&sW[idx]) = *reinterpret_cast<const float4*>(&W[idx]);
    __syncthreads();

    const int warp = tid >> 5, lane = tid & 31;
    const int r0 = warp * 8;
    float2 acc[8];
#pragma unroll
    for (int r = 0; r < 8; r++) acc[r] = make_float2(0.f, 0.f);

#pragma unroll 2
    for (int k4 = 0; k4 < K; k4 += 4) {
        float2 w0 = *reinterpret_cast<const float2*>(&sW[(k4 + 0) * 64 + 2 * lane]);
        float2 w1 = *reinterpret_cast<const float2*>(&sW[(k4 + 1) * 64 + 2 * lane]);
        float2 w2 = *reinterpret_cast<const float2*>(&sW[(k4 + 2) * 64 + 2 * lane]);
        float2 w3 = *reinterpret_cast<const float2*>(&sW[(k4 + 3) * 64 + 2 * lane]);
#pragma unroll
        for (int r = 0; r < 8; r++) {
            float4 av = *reinterpret_cast<const float4*>(&sA[(r0 + r) * K + k4]);
            acc[r] = ffma2(av.x, w0, acc[r]);
            acc[r] = ffma2(av.y, w1, acc[r]);
            acc[r] = ffma2(av.z, w2, acc[r]);
            acc[r] = ffma2(av.w, w3, acc[r]);
        }
    }

    const float2 bv = *reinterpret_cast<const float2*>(&bias[2 * lane]);
    float2 gv = make_float2(1.f, 1.f), tv = make_float2(0.f, 0.f);
    if (zout) {
        gv = *reinterpret_cast<const float2*>(&png[2 * lane]);
        tv = *reinterpret_cast<const float2*>(&pnb[2 * lane]);
    }
#pragma unroll
    for (int r = 0; r < 8; r++) {
        int row = m0 + r0 + r;
        if (row >= M) break;  // warp-uniform
        float2 o = make_float2(acc[r].x + bv.x, acc[r].y + bv.y);
        if (resid) {
            float2 rv = *reinterpret_cast<const float2*>(&resid[(size_t)row * 64 + 2 * lane]);
            o.x += rv.x;
            o.y += rv.y;
        }
        *reinterpret_cast<float2*>(&hout[(size_t)row * 64 + 2 * lane]) = o;
        if (zout) {
            float s1 = o.x + o.y;
            float s2 = o.x * o.x + o.y * o.y;
#pragma unroll
            for (int off = 16; off; off >>= 1) {
                s1 += __shfl_xor_sync(0xffffffffu, s1, off);
                s2 += __shfl_xor_sync(0xffffffffu, s2, off);
            }
            float mean = s1 * (1.f / 64.f);
            float var = s2 * (1.f / 64.f) - mean * mean;
            float rstd = rsqrtf(var + LN_EPS);
            float z0 = fmaxf((o.x - mean) * rstd * gv.x + tv.x, 0.f);
            float z1 = fmaxf((o.y - mean) * rstd * gv.y + tv.y, 0.f);
            *reinterpret_cast<float2*>(&zout[(size_t)row * 64 + 2 * lane]) =
                make_float2(z0, z1);
        }
    }
}

// ---------------- GEMM NOUT=128, K=64, fused LN(128)+ReLU ---------------------
// lane owns features {4l..4l+3}.
__global__ __launch_bounds__(256) void gemm128_kernel(const float* __restrict__ A,
                                                      const float* __restrict__ W,
                                                      const float* __restrict__ bias,
                                                      const float* __restrict__ lng,
                                                      const float* __restrict__ lnb,
                                                      float* __restrict__ C, int M) {
    constexpr int K = 64;
    extern __shared__ float sh[];
    float* sA = sh;             // 64*64
    float* sW = sh + 64 * K;    // 64*128
    const int tid = threadIdx.x;
    const int m0 = blockIdx.x * 64;

    for (int idx = tid * 4; idx < 64 * K; idx += 1024) {
        int row = idx / K, col = idx % K;
        float4 v = make_float4(0.f, 0.f, 0.f, 0.f);
        if (m0 + row < M)
            v = *reinterpret_cast<const float4*>(&A[(size_t)(m0 + row) * K + col]);
        *reinterpret_cast<float4*>(&sA[idx]) = v;
    }
    for (int idx = tid * 4; idx < K * 128; idx += 1024)
        *reinterpret_cast<float4*>(&sW[idx]) = *reinterpret_cast<const float4*>(&W[idx]);
    __syncthreads();

    const int warp = tid >> 5, lane = tid & 31;
    const int r0 = warp * 8;
    float2 acc[8][2];
#pragma unroll
    for (int r = 0; r < 8; r++) {
        acc[r][0] = make_float2(0.f, 0.f);
        acc[r][1] = make_float2(0.f, 0.f);
    }

#pragma unroll 2
    for (int k4 = 0; k4 < K; k4 += 4) {
        float4 wa = *reinterpret_cast<const float4*>(&sW[(k4 + 0) * 128 + 4 * lane]);
        float4 wb = *reinterpret_cast<const float4*>(&sW[(k4 + 1) * 128 + 4 * lane]);
        float4 wc = *reinterpret_cast<const float4*>(&sW[(k4 + 2) * 128 + 4 * lane]);
        float4 wd = *reinterpret_cast<const float4*>(&sW[(k4 + 3) * 128 + 4 * lane]);
#pragma unroll
        for (int r = 0; r < 8; r++) {
            float4 av = *reinterpret_cast<const float4*>(&sA[(r0 + r) * K + k4]);
            acc[r][0] = ffma2(av.x, make_float2(wa.x, wa.y), acc[r][0]);
            acc[r][1] = ffma2(av.x, make_float2(wa.z, wa.w), acc[r][1]);
            acc[r][0] = ffma2(av.y, make_float2(wb.x, wb.y), acc[r][0]);
            acc[r][1] = ffma2(av.y, make_float2(wb.z, wb.w), acc[r][1]);
            acc[r][0] = ffma2(av.z, make_float2(wc.x, wc.y), acc[r][0]);
            acc[r][1] = ffma2(av.z, make_float2(wc.z, wc.w), acc[r][1]);
            acc[r][0] = ffma2(av.w, make_float2(wd.x, wd.y), acc[r][0]);
            acc[r][1] = ffma2(av.w, make_float2(wd.z, wd.w), acc[r][1]);
        }
    }

    const float4 bv = *reinterpret_cast<const float4*>(&bias[4 * lane]);
    const float4 gv = *reinterpret_cast<const float4*>(&lng[4 * lane]);
    const float4 tv = *reinterpret_cast<const float4*>(&lnb[4 * lane]);
#pragma unroll
    for (int r = 0; r < 8; r++) {
        int row = m0 + r0 + r;
        if (row >= M) break;  // warp-uniform
        float v0 = acc[r][0].x + bv.x, v1 = acc[r][0].y + bv.y;
        float v2 = acc[r][1].x + bv.z, v3 = acc[r][1].y + bv.w;
        float s1 = v0 + v1 + v2 + v3;
        float s2 = v0 * v0 + v1 * v1 + v2 * v2 + v3 * v3;
#pragma unroll
        for (int off = 16; off; off >>= 1) {
            s1 += __shfl_xor_sync(0xffffffffu, s1, off);
            s2 += __shfl_xor_sync(0xffffffffu, s2, off);
        }
        float mean = s1 * (1.f / 128.f);
        float var = s2 * (1.f / 128.f) - mean * mean;
        float rstd = rsqrtf(var + LN_EPS);
        v0 = fmaxf((v0 - mean) * rstd * gv.x + tv.x, 0.f);
        v1 = fmaxf((v1 - mean) * rstd * gv.y + tv.y, 0.f);
        v2 = fmaxf((v2 - mean) * rstd * gv.z + tv.z, 0.f);
        v3 = fmaxf((v3 - mean) * rstd * gv.w + tv.w, 0.f);
        *reinterpret_cast<float4*>(&C[(size_t)row * 128 + 4 * lane]) =
            make_float4(v0, v1, v2, v3);
    }
}

// ---------------- launch ------------------------------------------------------
extern "C" void kernel_launch(void* const* d_in, const int* in_sizes, int n_in,
                              void* d_out, int out_size) {
    const float* x      = (const float*)d_in[0];
    const int*   ei     = (const int*)d_in[1];
    const float* eattr  = (const float*)d_in[2];
    const float* node_W = (const float*)d_in[3];
    const float* node_b = (const float*)d_in[4];
    const float* edge_W = (const float*)d_in[5];
    const float* edge_b = (const float*)d_in[6];
    const float* t      = (const float*)d_in[7];
    const float* mlp1_W = (const float*)d_in[8];
    const float* mlp1_b = (const float*)d_in[9];
    const float* ln_g   = (const float*)d_in[10];
    const float* ln_b   = (const float*)d_in[11];
    const float* mlp2_W = (const float*)d_in[12];
    const float* mlp2_b = (const float*)d_in[13];
    const float* blk_g  = (const float*)d_in[14];
    const float* blk_b  = (const float*)d_in[15];
    float* out = (float*)d_out;

    const int* src = ei;
    const int* dst = ei + EE;

    float *p_pe, *p_h, *p_z, *p_agg, *p_t1;
    int *p_deg, *p_rowptr, *p_cursor, *p_psrc;
    cudaGetSymbolAddress((void**)&p_pe, g_pe);
    cudaGetSymbolAddress((void**)&p_h, g_h);
    cudaGetSymbolAddress((void**)&p_z, g_z);
    cudaGetSymbolAddress((void**)&p_agg, g_agg);
    cudaGetSymbolAddress((void**)&p_t1, g_t1);
    cudaGetSymbolAddress((void**)&p_deg, g_deg);
    cudaGetSymbolAddress((void**)&p_rowptr, g_rowptr);
    cudaGetSymbolAddress((void**)&p_cursor, g_cursor);
    cudaGetSymbolAddress((void**)&p_psrc, g_psrc);

    cudaFuncSetAttribute(gemm64_kernel<128>,
                         cudaFuncAttributeMaxDynamicSharedMemorySize, 65536);
    cudaFuncSetAttribute(gemm128_kernel,
                         cudaFuncAttributeMaxDynamicSharedMemorySize, 49152);

    const int warpBlocks = (NN * 32 + 255) / 256;  // 6250 (one warp per node)
    const int gemmBlocks = (NN + 63) / 64;         // 782

    // --- CSR build + edge_attr permutation (reused across all layers) ---
    cudaMemsetAsync(p_deg, 0, NN * sizeof(int));
    hist_kernel<<<(EE + 255) / 256, 256>>>(dst, p_deg);
    scan_kernel<<<1, 1024>>>(p_deg, p_rowptr, p_cursor);
    scatter_kernel<<<(EE + 255) / 256, 256>>>(src, dst, eattr, p_cursor, p_psrc, p_pe);

    // --- node encoder: h = x @ node_W + node_b ---
    gemm64_kernel<128><<<gemmBlocks, 256, 65536>>>(
        x, node_W, node_b, nullptr, p_h, nullptr, nullptr, nullptr, NN);

    // --- layers (z for layer i+1, and the final output, are fused into gemm2) ---
    for (int i = 0; i < LL; i++) {
        const float* zin = (i == 0) ? p_h : p_z;
        agg_kernel<<<warpBlocks, 256>>>(zin, p_pe, p_psrc, p_rowptr,
                                        edge_W, edge_b, t + i, p_agg);
        gemm128_kernel<<<gemmBlocks, 256, 49152>>>(
            p_agg, mlp1_W + (size_t)i * 64 * 128, mlp1_b + i * 128,
            ln_g + i * 128, ln_b + i * 128, p_t1, NN);
        const bool last = (i == LL - 1);
        const float* png = last ? blk_g : blk_g + (i + 1) * HH;  // final norm uses blk[0]
        const float* pnb = last ? blk_b : blk_b + (i + 1) * HH;
        float* zo = last ? out : p_z;
        gemm64_kernel<128><<<gemmBlocks, 256, 65536>>>(
            p_t1, mlp2_W + (size_t)i * 128 * 64, mlp2_b + i * 64,
            (i > 0 ? p_h : nullptr), p_h, png, pnb, zo, NN);
    }
}

// round 7
// speedup vs baseline: 1.2432x; 1.2432x over previous
#include <cuda_runtime.h>
#include <cuda_fp16.h>
#include <cstddef>

// Problem constants (fixed by the dataset)
#define NN 50000
#define EE 800000
#define HH 64      // hidden
#define DC 128     // node in channels
#define EC 16      // edge in channels
#define LL 3
#define EPS_MSG 1e-7f
#define LN_EPS 1e-5f

// ---------------- device scratch (no cudaMalloc allowed) ----------------
__device__ __half2 g_ea2[(size_t)EE * (HH / 2)];  // CSR-ordered encoded edges, fp16, 102.4 MB
__device__ float g_h[(size_t)NN * HH];            // node state
__device__ float g_z[(size_t)NN * HH];            // pre-normed layer input
__device__ float g_agg[(size_t)NN * HH];          // conv output (agg + root)
__device__ float g_t1[(size_t)NN * 2 * HH];       // MLP hidden
__device__ int   g_deg[NN];
__device__ int   g_rowptr[NN + 1];
__device__ int   g_cursor[NN];
__device__ int   g_psrc[EE];

// ---------------- packed f32x2 FMA helpers ----------------
__device__ __forceinline__ unsigned long long pk2(float x, float y) {
    unsigned long long r;
    asm("mov.b64 %0, {%1,%2};" : "=l"(r) : "f"(x), "f"(y));
    return r;
}
__device__ __forceinline__ float2 upk2(unsigned long long v) {
    float2 r;
    asm("mov.b64 {%0,%1}, %2;" : "=f"(r.x), "=f"(r.y) : "l"(v));
    return r;
}
// c += a * b (a splatted across the pair)
__device__ __forceinline__ float2 ffma2(float a, float2 b, float2 c) {
    unsigned long long ra = pk2(a, a);
    unsigned long long rb = pk2(b.x, b.y);
    unsigned long long rc = pk2(c.x, c.y);
    asm("fma.rn.f32x2 %0, %1, %2, %0;" : "+l"(rc) : "l"(ra), "l"(rb));
    return upk2(rc);
}

// ---------------- CSR build ---------------------------------------------------
__global__ void hist_kernel(const int* __restrict__ dst, int* __restrict__ deg) {
    int e = blockIdx.x * blockDim.x + threadIdx.x;
    if (e < EE) atomicAdd(&deg[dst[e]], 1);
}

__global__ void scan_kernel(const int* __restrict__ deg, int* __restrict__ rowptr,
                            int* __restrict__ cursor) {
    __shared__ int sh[1024];
    const int tid = threadIdx.x;
    const int CH = (NN + 1023) / 1024;
    const int base = tid * CH;
    int s = 0;
    for (int i = 0; i < CH; i++) {
        int j = base + i;
        if (j < NN) s += deg[j];
    }
    sh[tid] = s;
    __syncthreads();
    for (int off = 1; off < 1024; off <<= 1) {
        int v = (tid >= off) ? sh[tid - off] : 0;
        __syncthreads();
        sh[tid] += v;
        __syncthreads();
    }
    int run = (tid > 0) ? sh[tid - 1] : 0;
    for (int i = 0; i < CH; i++) {
        int j = base + i;
        if (j < NN) {
            rowptr[j] = run;
            cursor[j] = run;
            run += deg[j];
        }
    }
    if (tid == 0) rowptr[NN] = sh[1023];
}

// ---------------- fused scatter + edge encoder --------------------------------
// Warp per edge. Computes ea = eattr @ edge_W + edge_b ONCE (not per layer) and
// writes it fp16 directly into its CSR-permuted slot. edge_W lives in registers.
__global__ __launch_bounds__(256) void scatter_enc_kernel(const int* __restrict__ src,
                                                          const int* __restrict__ dst,
                                                          const float* __restrict__ eattr,
                                                          const float* __restrict__ eW,
                                                          const float* __restrict__ eb,
                                                          int* __restrict__ cursor,
                                                          int* __restrict__ psrc,
                                                          __half2* __restrict__ ea2) {
    const int lane = threadIdx.x & 31;
    float2 Wr[EC];
#pragma unroll
    for (int k = 0; k < EC; k++)
        Wr[k] = *reinterpret_cast<const float2*>(&eW[k * HH + 2 * lane]);
    const float2 bv = *reinterpret_cast<const float2*>(&eb[2 * lane]);

    int gw = (blockIdx.x * blockDim.x + threadIdx.x) >> 5;
    const int nw = (gridDim.x * blockDim.x) >> 5;
    for (int e = gw; e < EE; e += nw) {
        float a = (lane < EC) ? eattr[(size_t)e * EC + lane] : 0.f;
        int idx = 0;
        if (lane == 0) idx = atomicAdd(&cursor[dst[e]], 1);
        idx = __shfl_sync(0xffffffffu, idx, 0);
        if (lane == 0) psrc[idx] = src[e];
        float2 ev0 = bv, ev1 = make_float2(0.f, 0.f);
#pragma unroll
        for (int k = 0; k < EC; k += 2) {
            ev0 = ffma2(__shfl_sync(0xffffffffu, a, k), Wr[k], ev0);
            ev1 = ffma2(__shfl_sync(0xffffffffu, a, k + 1), Wr[k + 1], ev1);
        }
        float2 ev = make_float2(ev0.x + ev1.x, ev0.y + ev1.y);
        ea2[(size_t)idx * 32 + lane] = __float22half2_rn(ev);
    }
}

// ---------------- softmax aggregation (streaming fp16 ea) ---------------------
// One warp per destination node; lane owns features {2l,2l+1}. ea reads are
// fully sequential (CSR order). psrc prefetched 2 ahead so the dependent random
// z gather can be issued 1 ahead.
__global__ __launch_bounds__(256, 6) void agg_kernel(const float* __restrict__ z,
                                                     const __half2* __restrict__ ea2,
                                                     const int* __restrict__ psrc,
                                                     const int* __restrict__ rowptr,
                                                     const float* __restrict__ t_ptr,
                                                     float* __restrict__ out) {
    const int w = (blockIdx.x * blockDim.x + threadIdx.x) >> 5;
    if (w >= NN) return;
    const int lane = threadIdx.x & 31;
    const float t = *t_ptr;

    const int beg = rowptr[w], end = rowptr[w + 1];
    float2 accP = make_float2(0.f, 0.f);
    float2 accM = make_float2(0.f, 0.f);

    __half2 eA = __float2half2_rn(0.f);
    float2 zA = make_float2(0.f, 0.f);
    int sB = 0;
    if (beg < end) {
        int sA = psrc[beg];
        eA = ea2[(size_t)beg * 32 + lane];
        zA = *reinterpret_cast<const float2*>(&z[(size_t)sA * HH + 2 * lane]);
        if (beg + 1 < end) sB = psrc[beg + 1];
    }

    for (int j = beg; j < end; j++) {
        // prefetch stage j+1 (z via sB loaded last iter) and psrc for j+2
        __half2 eB = __float2half2_rn(0.f);
        float2 zB = make_float2(0.f, 0.f);
        int sC = 0;
        if (j + 1 < end) {
            eB = ea2[(size_t)(j + 1) * 32 + lane];
            zB = *reinterpret_cast<const float2*>(&z[(size_t)sB * HH + 2 * lane]);
        }
        if (j + 2 < end) sC = psrc[j + 2];

        float2 ev = __half22float2(eA);
        float m0 = fmaxf(zA.x + ev.x, 0.f) + EPS_MSG;
        float m1 = fmaxf(zA.y + ev.y, 0.f) + EPS_MSG;
        // softmax without max-shift: exp args bounded (msg small, t = O(1))
        float p0 = __expf(m0 * t);
        float p1 = __expf(m1 * t);
        accP.x += p0;
        accP.y += p1;
        accM.x = fmaf(m0, p0, accM.x);
        accM.y = fmaf(m1, p1, accM.y);

        eA = eB;
        zA = zB;
        sB = sC;
    }
    float2 zd = *reinterpret_cast<const float2*>(&z[(size_t)w * HH + 2 * lane]);
    float2 o;
    o.x = (end > beg ? accM.x / accP.x : 0.f) + zd.x;
    o.y = (end > beg ? accM.y / accP.y : 0.f) + zd.y;
    *reinterpret_cast<float2*>(&out[(size_t)w * HH + 2 * lane]) = o;
}

// ---------------- GEMM NOUT=64, K=128, K-chunked smem (32 KB) -----------------
// C = A[M,128] @ W[128,64] + bias (+resid). hout = raw; if zout!=null also
// writes zout = relu(LayerNorm64(hout)). Warp owns 8 rows, lane feats {2l,2l+1}.
__global__ __launch_bounds__(256, 6) void gemm64_kernel(const float* __restrict__ A,
                                                        const float* __restrict__ W,
                                                        const float* __restrict__ bias,
                                                        const float* __restrict__ resid,
                                                        float* __restrict__ hout,
                                                        const float* __restrict__ png,
                                                        const float* __restrict__ pnb,
                                                        float* __restrict__ zout, int M) {
    constexpr int K = 128, KC = 64;
    __shared__ float sA[64 * KC];  // 16 KB
    __shared__ float sW[KC * 64];  // 16 KB
    const int tid = threadIdx.x;
    const int m0 = blockIdx.x * 64;
    const int warp = tid >> 5, lane = tid & 31;
    const int r0 = warp * 8;

    float2 acc[8];
#pragma unroll
    for (int r = 0; r < 8; r++) acc[r] = make_float2(0.f, 0.f);

#pragma unroll
    for (int kc = 0; kc < K; kc += KC) {
        if (kc) __syncthreads();
        for (int idx = tid * 4; idx < 64 * KC; idx += 1024) {
            int row = idx / KC, col = idx % KC;
            float4 v = make_float4(0.f, 0.f, 0.f, 0.f);
            if (m0 + row < M)
                v = *reinterpret_cast<const float4*>(&A[(size_t)(m0 + row) * K + kc + col]);
            *reinterpret_cast<float4*>(&sA[idx]) = v;
        }
        for (int idx = tid * 4; idx < KC * 64; idx += 1024) {
            int row = idx / 64, col = idx % 64;
            *reinterpret_cast<float4*>(&sW[idx]) =
                *reinterpret_cast<const float4*>(&W[(kc + row) * 64 + col]);
        }
        __syncthreads();

#pragma unroll 4
        for (int k4 = 0; k4 < KC; k4 += 4) {
            float2 w0 = *reinterpret_cast<const float2*>(&sW[(k4 + 0) * 64 + 2 * lane]);
            float2 w1 = *reinterpret_cast<const float2*>(&sW[(k4 + 1) * 64 + 2 * lane]);
            float2 w2 = *reinterpret_cast<const float2*>(&sW[(k4 + 2) * 64 + 2 * lane]);
            float2 w3 = *reinterpret_cast<const float2*>(&sW[(k4 + 3) * 64 + 2 * lane]);
#pragma unroll
            for (int r = 0; r < 8; r++) {
                float4 av = *reinterpret_cast<const float4*>(&sA[(r0 + r) * KC + k4]);
                acc[r] = ffma2(av.x, w0, acc[r]);
                acc[r] = ffma2(av.y, w1, acc[r]);
                acc[r] = ffma2(av.z, w2, acc[r]);
                acc[r] = ffma2(av.w, w3, acc[r]);
            }
        }
    }

    const float2 bv = *reinterpret_cast<const float2*>(&bias[2 * lane]);
    float2 gv = make_float2(1.f, 1.f), tv = make_float2(0.f, 0.f);
    if (zout) {
        gv = *reinterpret_cast<const float2*>(&png[2 * lane]);
        tv = *reinterpret_cast<const float2*>(&pnb[2 * lane]);
    }
#pragma unroll
    for (int r = 0; r < 8; r++) {
        int row = m0 + r0 + r;
        if (row >= M) break;  // warp-uniform
        float2 o = make_float2(acc[r].x + bv.x, acc[r].y + bv.y);
        if (resid) {
            float2 rv = *reinterpret_cast<const float2*>(&resid[(size_t)row * 64 + 2 * lane]);
            o.x += rv.x;
            o.y += rv.y;
        }
        *reinterpret_cast<float2*>(&hout[(size_t)row * 64 + 2 * lane]) = o;
        if (zout) {
            float s1 = o.x + o.y;
            float s2 = o.x * o.x + o.y * o.y;
#pragma unroll
            for (int off = 16; off; off >>= 1) {
                s1 += __shfl_xor_sync(0xffffffffu, s1, off);
                s2 += __shfl_xor_sync(0xffffffffu, s2, off);
            }
            float mean = s1 * (1.f / 64.f);
            float var = s2 * (1.f / 64.f) - mean * mean;
            float rstd = rsqrtf(var + LN_EPS);
            float z0 = fmaxf((o.x - mean) * rstd * gv.x + tv.x, 0.f);
            float z1 = fmaxf((o.y - mean) * rstd * gv.y + tv.y, 0.f);
            *reinterpret_cast<float2*>(&zout[(size_t)row * 64 + 2 * lane]) =
                make_float2(z0, z1);
        }
    }
}

// ---------------- GEMM NOUT=128, K=64, K-chunked smem (24 KB), fused LN+ReLU --
// lane owns features {4l..4l+3}.
__global__ __launch_bounds__(256, 4) void gemm128_kernel(const float* __restrict__ A,
                                                         const float* __restrict__ W,
                                                         const float* __restrict__ bias,
                                                         const float* __restrict__ lng,
                                                         const float* __restrict__ lnb,
                                                         float* __restrict__ C, int M) {
    constexpr int K = 64, KC = 32;
    __shared__ float sA[64 * KC];   // 8 KB
    __shared__ float sW[KC * 128];  // 16 KB
    const int tid = threadIdx.x;
    const int m0 = blockIdx.x * 64;
    const int warp = tid >> 5, lane = tid & 31;
    const int r0 = warp * 8;

    float2 acc[8][2];
#pragma unroll
    for (int r = 0; r < 8; r++) {
        acc[r][0] = make_float2(0.f, 0.f);
        acc[r][1] = make_float2(0.f, 0.f);
    }

#pragma unroll
    for (int kc = 0; kc < K; kc += KC) {
        if (kc) __syncthreads();
        for (int idx = tid * 4; idx < 64 * KC; idx += 1024) {
            int row = idx / KC, col = idx % KC;
            float4 v = make_float4(0.f, 0.f, 0.f, 0.f);
            if (m0 + row < M)
                v = *reinterpret_cast<const float4*>(&A[(size_t)(m0 + row) * K + kc + col]);
            *reinterpret_cast<float4*>(&sA[idx]) = v;
        }
        for (int idx = tid * 4; idx < KC * 128; idx += 1024) {
            int row = idx / 128, col = idx % 128;
            *reinterpret_cast<float4*>(&sW[idx]) =
                *reinterpret_cast<const float4*>(&W[(kc + row) * 128 + col]);
        }
        __syncthreads();

#pragma unroll 2
        for (int k4 = 0; k4 < KC; k4 += 4) {
            float4 wa = *reinterpret_cast<const float4*>(&sW[(k4 + 0) * 128 + 4 * lane]);
            float4 wb = *reinterpret_cast<const float4*>(&sW[(k4 + 1) * 128 + 4 * lane]);
            float4 wc = *reinterpret_cast<const float4*>(&sW[(k4 + 2) * 128 + 4 * lane]);
            float4 wd = *reinterpret_cast<const float4*>(&sW[(k4 + 3) * 128 + 4 * lane]);
#pragma unroll
            for (int r = 0; r < 8; r++) {
                float4 av = *reinterpret_cast<const float4*>(&sA[(r0 + r) * KC + k4]);
                acc[r][0] = ffma2(av.x, make_float2(wa.x, wa.y), acc[r][0]);
                acc[r][1] = ffma2(av.x, make_float2(wa.z, wa.w), acc[r][1]);
                acc[r][0] = ffma2(av.y, make_float2(wb.x, wb.y), acc[r][0]);
                acc[r][1] = ffma2(av.y, make_float2(wb.z, wb.w), acc[r][1]);
                acc[r][0] = ffma2(av.z, make_float2(wc.x, wc.y), acc[r][0]);
                acc[r][1] = ffma2(av.z, make_float2(wc.z, wc.w), acc[r][1]);
                acc[r][0] = ffma2(av.w, make_float2(wd.x, wd.y), acc[r][0]);
                acc[r][1] = ffma2(av.w, make_float2(wd.z, wd.w), acc[r][1]);
            }
        }
    }

    const float4 bv = *reinterpret_cast<const float4*>(&bias[4 * lane]);
    const float4 gv = *reinterpret_cast<const float4*>(&lng[4 * lane]);
    const float4 tv = *reinterpret_cast<const float4*>(&lnb[4 * lane]);
#pragma unroll
    for (int r = 0; r < 8; r++) {
        int row = m0 + r0 + r;
        if (row >= M) break;  // warp-uniform
        float v0 = acc[r][0].x + bv.x, v1 = acc[r][0].y + bv.y;
        float v2 = acc[r][1].x + bv.z, v3 = acc[r][1].y + bv.w;
        float s1 = v0 + v1 + v2 + v3;
        float s2 = v0 * v0 + v1 * v1 + v2 * v2 + v3 * v3;
#pragma unroll
        for (int off = 16; off; off >>= 1) {
            s1 += __shfl_xor_sync(0xffffffffu, s1, off);
            s2 += __shfl_xor_sync(0xffffffffu, s2, off);
        }
        float mean = s1 * (1.f / 128.f);
        float var = s2 * (1.f / 128.f) - mean * mean;
        float rstd = rsqrtf(var + LN_EPS);
        v0 = fmaxf((v0 - mean) * rstd * gv.x + tv.x, 0.f);
        v1 = fmaxf((v1 - mean) * rstd * gv.y + tv.y, 0.f);
        v2 = fmaxf((v2 - mean) * rstd * gv.z + tv.z, 0.f);
        v3 = fmaxf((v3 - mean) * rstd * gv.w + tv.w, 0.f);
        *reinterpret_cast<float4*>(&C[(size_t)row * 128 + 4 * lane]) =
            make_float4(v0, v1, v2, v3);
    }
}

// ---------------- launch ------------------------------------------------------
extern "C" void kernel_launch(void* const* d_in, const int* in_sizes, int n_in,
                              void* d_out, int out_size) {
    const float* x      = (const float*)d_in[0];
    const int*   ei     = (const int*)d_in[1];
    const float* eattr  = (const float*)d_in[2];
    const float* node_W = (const float*)d_in[3];
    const float* node_b = (const float*)d_in[4];
    const float* edge_W = (const float*)d_in[5];
    const float* edge_b = (const float*)d_in[6];
    const float* t      = (const float*)d_in[7];
    const float* mlp1_W = (const float*)d_in[8];
    const float* mlp1_b = (const float*)d_in[9];
    const float* ln_g   = (const float*)d_in[10];
    const float* ln_b   = (const float*)d_in[11];
    const float* mlp2_W = (const float*)d_in[12];
    const float* mlp2_b = (const float*)d_in[13];
    const float* blk_g  = (const float*)d_in[14];
    const float* blk_b  = (const float*)d_in[15];
    float* out = (float*)d_out;

    const int* src = ei;
    const int* dst = ei + EE;

    __half2* p_ea2;
    float *p_h, *p_z, *p_agg, *p_t1;
    int *p_deg, *p_rowptr, *p_cursor, *p_psrc;
    cudaGetSymbolAddress((void**)&p_ea2, g_ea2);
    cudaGetSymbolAddress((void**)&p_h, g_h);
    cudaGetSymbolAddress((void**)&p_z, g_z);
    cudaGetSymbolAddress((void**)&p_agg, g_agg);
    cudaGetSymbolAddress((void**)&p_t1, g_t1);
    cudaGetSymbolAddress((void**)&p_deg, g_deg);
    cudaGetSymbolAddress((void**)&p_rowptr, g_rowptr);
    cudaGetSymbolAddress((void**)&p_cursor, g_cursor);
    cudaGetSymbolAddress((void**)&p_psrc, g_psrc);

    const int warpBlocks = (NN * 32 + 255) / 256;  // 6250 (one warp per node)
    const int gemmBlocks = (NN + 63) / 64;         // 782

    // --- CSR build + fused edge encode into permuted fp16 slots ---
    cudaMemsetAsync(p_deg, 0, NN * sizeof(int));
    hist_kernel<<<(EE + 255) / 256, 256>>>(dst, p_deg);
    scan_kernel<<<1, 1024>>>(p_deg, p_rowptr, p_cursor);
    scatter_enc_kernel<<<4096, 256>>>(src, dst, eattr, edge_W, edge_b,
                                      p_cursor, p_psrc, p_ea2);

    // --- node encoder: h = x @ node_W + node_b ---
    gemm64_kernel<<<gemmBlocks, 256>>>(x, node_W, node_b, nullptr, p_h,
                                       nullptr, nullptr, nullptr, NN);

    // --- layers (next layer's pre-norm z and the final output fused into gemm2) ---
    for (int i = 0; i < LL; i++) {
        const float* zin = (i == 0) ? p_h : p_z;
        agg_kernel<<<warpBlocks, 256>>>(zin, p_ea2, p_psrc, p_rowptr, t + i, p_agg);
        gemm128_kernel<<<gemmBlocks, 256>>>(
            p_agg, mlp1_W + (size_t)i * 64 * 128, mlp1_b + i * 128,
            ln_g + i * 128, ln_b + i * 128, p_t1, NN);
        const bool last = (i == LL - 1);
        const float* png = last ? blk_g : blk_g + (i + 1) * HH;  // final norm uses blk[0]
        const float* pnb = last ? blk_b : blk_b + (i + 1) * HH;
        float* zo = last ? out : p_z;
        gemm64_kernel<<<gemmBlocks, 256>>>(
            p_t1, mlp2_W + (size_t)i * 128 * 64, mlp2_b + i * 64,
            (i > 0 ? p_h : nullptr), p_h, png, pnb, zo, NN);
    }
}

// round 10
// speedup vs baseline: 1.2756x; 1.0260x over previous
#include <cuda_runtime.h>
#include <cuda_fp16.h>
#include <cstddef>

// Problem constants (fixed by the dataset)
#define NN 50000
#define EE 800000
#define HH 64      // hidden
#define DC 128     // node in channels
#define EC 16      // edge in channels
#define LL 3
#define EPS_MSG 1e-7f
#define LN_EPS 1e-5f

#define NCHUNK ((NN + 255) / 256)   // 196

// ---------------- device scratch (no cudaMalloc allowed) ----------------
__device__ __half2 g_ea2[(size_t)EE * (HH / 2)];  // CSR-ordered encoded edges, fp16, 102.4 MB
__device__ float g_h[(size_t)NN * HH];            // node state
__device__ float g_z[(size_t)NN * HH];            // pre-normed layer input
__device__ float g_agg[(size_t)NN * HH];          // conv output (agg + root)
__device__ float g_t1[(size_t)NN * 2 * HH];       // MLP hidden
__device__ int   g_deg[NN];
__device__ int   g_rowptr[NN + 1];
__device__ int   g_cursor[NN];
__device__ int   g_psrc[EE];
__device__ int   g_bsum[256];
__device__ int   g_boff[256];

// ---------------- packed f32x2 FMA helpers ----------------
__device__ __forceinline__ unsigned long long pk2(float x, float y) {
    unsigned long long r;
    asm("mov.b64 %0, {%1,%2};" : "=l"(r) : "f"(x), "f"(y));
    return r;
}
__device__ __forceinline__ float2 upk2(unsigned long long v) {
    float2 r;
    asm("mov.b64 {%0,%1}, %2;" : "=f"(r.x), "=f"(r.y) : "l"(v));
    return r;
}
// c += a * b (a splatted across the pair)
__device__ __forceinline__ float2 ffma2(float a, float2 b, float2 c) {
    unsigned long long ra = pk2(a, a);
    unsigned long long rb = pk2(b.x, b.y);
    unsigned long long rc = pk2(c.x, c.y);
    asm("fma.rn.f32x2 %0, %1, %2, %0;" : "+l"(rc) : "l"(ra), "l"(rb));
    return upk2(rc);
}

// ---------------- CSR build (parallel) ----------------------------------------
__global__ void hist_kernel(const int* __restrict__ dst, int* __restrict__ deg) {
    int e = blockIdx.x * blockDim.x + threadIdx.x;
    if (e < EE) atomicAdd(&deg[dst[e]], 1);
}

__global__ void chunk_sum_kernel(const int* __restrict__ deg, int* __restrict__ bsum) {
    __shared__ int sh[256];
    int t = threadIdx.x;
    int i = blockIdx.x * 256 + t;
    sh[t] = (i < NN) ? deg[i] : 0;
    __syncthreads();
#pragma unroll
    for (int off = 128; off; off >>= 1) {
        if (t < off) sh[t] += sh[t + off];
        __syncthreads();
    }
    if (t == 0) bsum[blockIdx.x] = sh[0];
}

__global__ void chunk_scan_kernel(const int* __restrict__ bsum, int* __restrict__ boff) {
    __shared__ int sh[256];
    int t = threadIdx.x;
    int v = (t < NCHUNK) ? bsum[t] : 0;
    sh[t] = v;
    __syncthreads();
#pragma unroll
    for (int off = 1; off < 256; off <<= 1) {
        int u = (t >= off) ? sh[t - off] : 0;
        __syncthreads();
        sh[t] += u;
        __syncthreads();
    }
    if (t < NCHUNK) boff[t] = sh[t] - v;  // exclusive
}

__global__ void rowptr_kernel(const int* __restrict__ deg, const int* __restrict__ boff,
                              int* __restrict__ rowptr, int* __restrict__ cursor) {
    __shared__ int sh[256];
    int t = threadIdx.x;
    int i = blockIdx.x * 256 + t;
    int v = (i < NN) ? deg[i] : 0;
    sh[t] = v;
    __syncthreads();
#pragma unroll
    for (int off = 1; off < 256; off <<= 1) {
        int u = (t >= off) ? sh[t - off] : 0;
        __syncthreads();
        sh[t] += u;
        __syncthreads();
    }
    int excl = boff[blockIdx.x] + sh[t] - v;
    if (i < NN) {
        rowptr[i] = excl;
        cursor[i] = excl;
        if (i == NN - 1) rowptr[NN] = excl + v;
    }
}

// ---------------- fused scatter + edge encoder --------------------------------
// Warp per edge. Computes ea = eattr @ edge_W + edge_b ONCE and writes it fp16
// directly into its CSR-permuted slot. edge_W lives in registers.
__global__ __launch_bounds__(256) void scatter_enc_kernel(const int* __restrict__ src,
                                                          const int* __restrict__ dst,
                                                          const float* __restrict__ eattr,
                                                          const float* __restrict__ eW,
                                                          const float* __restrict__ eb,
                                                          int* __restrict__ cursor,
                                                          int* __restrict__ psrc,
                                                          __half2* __restrict__ ea2) {
    const int lane = threadIdx.x & 31;
    float2 Wr[EC];
#pragma unroll
    for (int k = 0; k < EC; k++)
        Wr[k] = *reinterpret_cast<const float2*>(&eW[k * HH + 2 * lane]);
    const float2 bv = *reinterpret_cast<const float2*>(&eb[2 * lane]);

    int gw = (blockIdx.x * blockDim.x + threadIdx.x) >> 5;
    const int nw = (gridDim.x * blockDim.x) >> 5;
    for (int e = gw; e < EE; e += nw) {
        float a = (lane < EC) ? eattr[(size_t)e * EC + lane] : 0.f;
        int idx = 0;
        if (lane == 0) idx = atomicAdd(&cursor[dst[e]], 1);
        idx = __shfl_sync(0xffffffffu, idx, 0);
        if (lane == 0) psrc[idx] = src[e];
        float2 ev0 = bv, ev1 = make_float2(0.f, 0.f);
#pragma unroll
        for (int k = 0; k < EC; k += 2) {
            ev0 = ffma2(__shfl_sync(0xffffffffu, a, k), Wr[k], ev0);
            ev1 = ffma2(__shfl_sync(0xffffffffu, a, k + 1), Wr[k + 1], ev1);
        }
        float2 ev = make_float2(ev0.x + ev1.x, ev0.y + ev1.y);
        ea2[(size_t)idx * 32 + lane] = __float22half2_rn(ev);
    }
}

// ---------------- softmax aggregation (depth-2 pipelined) ---------------------
// One warp per destination node; lane owns features {2l,2l+1}. ea is streamed
// sequentially (CSR order, fp16); the random z gather is kept 2 stages in
// flight so each warp has 2 L2-latency loads outstanding.
__global__ __launch_bounds__(256, 6) void agg_kernel(const float* __restrict__ z,
                                                     const __half2* __restrict__ ea2,
                                                     const int* __restrict__ psrc,
                                                     const int* __restrict__ rowptr,
                                                     const float* __restrict__ t_ptr,
                                                     float* __restrict__ out) {
    const int w = (blockIdx.x * blockDim.x + threadIdx.x) >> 5;
    if (w >= NN) return;
    const int lane = threadIdx.x & 31;
    const float t = *t_ptr;

    const int beg = rowptr[w], end = rowptr[w + 1];
    float2 accP = make_float2(0.f, 0.f);
    float2 accM = make_float2(0.f, 0.f);

    // pipeline registers: stage0 (compute), stage1 (in flight), src for j+2
    __half2 e0 = __float2half2_rn(0.f), e1 = e0;
    float2 z0 = make_float2(0.f, 0.f), z1 = z0;
    int s2 = 0;
    {
        int s0 = 0, s1 = 0;
        if (beg < end) s0 = psrc[beg];
        if (beg + 1 < end) s1 = psrc[beg + 1];
        if (beg + 2 < end) s2 = psrc[beg + 2];
        if (beg < end) {
            e0 = ea2[(size_t)beg * 32 + lane];
            z0 = *reinterpret_cast<const float2*>(&z[(size_t)s0 * HH + 2 * lane]);
        }
        if (beg + 1 < end) {
            e1 = ea2[(size_t)(beg + 1) * 32 + lane];
            z1 = *reinterpret_cast<const float2*>(&z[(size_t)s1 * HH + 2 * lane]);
        }
    }

    for (int j = beg; j < end; j++) {
        // issue stage j+2 loads; fetch psrc for j+3
        __half2 e2 = __float2half2_rn(0.f);
        float2 z2 = make_float2(0.f, 0.f);
        int s3 = 0;
        if (j + 2 < end) {
            e2 = ea2[(size_t)(j + 2) * 32 + lane];
            z2 = *reinterpret_cast<const float2*>(&z[(size_t)s2 * HH + 2 * lane]);
        }
        if (j + 3 < end) s3 = psrc[j + 3];

        float2 ev = __half22float2(e0);
        float m0 = fmaxf(z0.x + ev.x, 0.f) + EPS_MSG;
        float m1 = fmaxf(z0.y + ev.y, 0.f) + EPS_MSG;
        // softmax without max-shift: exp args bounded (msg small, t = O(1))
        float p0 = __expf(m0 * t);
        float p1 = __expf(m1 * t);
        accP.x += p0;
        accP.y += p1;
        accM.x = fmaf(m0, p0, accM.x);
        accM.y = fmaf(m1, p1, accM.y);

        e0 = e1; z0 = z1;
        e1 = e2; z1 = z2;
        s2 = s3;
    }
    float2 zd = *reinterpret_cast<const float2*>(&z[(size_t)w * HH + 2 * lane]);
    float2 o;
    o.x = (end > beg ? accM.x / accP.x : 0.f) + zd.x;
    o.y = (end > beg ? accM.y / accP.y : 0.f) + zd.y;
    *reinterpret_cast<float2*>(&out[(size_t)w * HH + 2 * lane]) = o;
}

// ---------------- GEMM NOUT=64, K=128, K-chunked smem (32 KB) -----------------
// C = A[M,128] @ W[128,64] + bias (+resid). hout = raw; if zout!=null also
// writes zout = relu(LayerNorm64(hout)). Warp owns 8 rows, lane feats {2l,2l+1}.
// Inner loops ordered (k-substep outer, rows inner) so same-accumulator updates
// are 8 independent instructions apart (RAW chain spacing > FFMA lat).
__global__ __launch_bounds__(256, 6) void gemm64_kernel(const float* __restrict__ A,
                                                        const float* __restrict__ W,
                                                        const float* __restrict__ bias,
                                                        const float* __restrict__ resid,
                                                        float* __restrict__ hout,
                                                        const float* __restrict__ png,
                                                        const float* __restrict__ pnb,
                                                        float* __restrict__ zout, int M) {
    constexpr int K = 128, KC = 64;
    __shared__ float sA[64 * KC];  // 16 KB
    __shared__ float sW[KC * 64];  // 16 KB
    const int tid = threadIdx.x;
    const int m0 = blockIdx.x * 64;
    const int warp = tid >> 5, lane = tid & 31;
    const int r0 = warp * 8;

    float2 acc[8];
#pragma unroll
    for (int r = 0; r < 8; r++) acc[r] = make_float2(0.f, 0.f);

#pragma unroll
    for (int kc = 0; kc < K; kc += KC) {
        if (kc) __syncthreads();
        for (int idx = tid * 4; idx < 64 * KC; idx += 1024) {
            int row = idx / KC, col = idx % KC;
            float4 v = make_float4(0.f, 0.f, 0.f, 0.f);
            if (m0 + row < M)
                v = *reinterpret_cast<const float4*>(&A[(size_t)(m0 + row) * K + kc + col]);
            *reinterpret_cast<float4*>(&sA[idx]) = v;
        }
        for (int idx = tid * 4; idx < KC * 64; idx += 1024) {
            int row = idx / 64, col = idx % 64;
            *reinterpret_cast<float4*>(&sW[idx]) =
                *reinterpret_cast<const float4*>(&W[(kc + row) * 64 + col]);
        }
        __syncthreads();

#pragma unroll 4
        for (int k4 = 0; k4 < KC; k4 += 4) {
            // batch all row A-fragments first (broadcast LDS.128)
            float4 av[8];
#pragma unroll
            for (int r = 0; r < 8; r++)
                av[r] = *reinterpret_cast<const float4*>(&sA[(r0 + r) * KC + k4]);
            float2 w0 = *reinterpret_cast<const float2*>(&sW[(k4 + 0) * 64 + 2 * lane]);
            float2 w1 = *reinterpret_cast<const float2*>(&sW[(k4 + 1) * 64 + 2 * lane]);
            float2 w2 = *reinterpret_cast<const float2*>(&sW[(k4 + 2) * 64 + 2 * lane]);
            float2 w3 = *reinterpret_cast<const float2*>(&sW[(k4 + 3) * 64 + 2 * lane]);
            // k-substep outer, rows inner: consecutive writes to acc[r] are 8 apart
#pragma unroll
            for (int r = 0; r < 8; r++) acc[r] = ffma2(av[r].x, w0, acc[r]);
#pragma unroll
            for (int r = 0; r < 8; r++) acc[r] = ffma2(av[r].y, w1, acc[r]);
#pragma unroll
            for (int r = 0; r < 8; r++) acc[r] = ffma2(av[r].z, w2, acc[r]);
#pragma unroll
            for (int r = 0; r < 8; r++) acc[r] = ffma2(av[r].w, w3, acc[r]);
        }
    }

    const float2 bv = *reinterpret_cast<const float2*>(&bias[2 * lane]);
    float2 gv = make_float2(1.f, 1.f), tv = make_float2(0.f, 0.f);
    if (zout) {
        gv = *reinterpret_cast<const float2*>(&png[2 * lane]);
        tv = *reinterpret_cast<const float2*>(&pnb[2 * lane]);
    }
#pragma unroll
    for (int r = 0; r < 8; r++) {
        int row = m0 + r0 + r;
        if (row >= M) break;  // warp-uniform
        float2 o = make_float2(acc[r].x + bv.x, acc[r].y + bv.y);
        if (resid) {
            float2 rv = *reinterpret_cast<const float2*>(&resid[(size_t)row * 64 + 2 * lane]);
            o.x += rv.x;
            o.y += rv.y;
        }
        *reinterpret_cast<float2*>(&hout[(size_t)row * 64 + 2 * lane]) = o;
        if (zout) {
            float s1 = o.x + o.y;
            float s2 = o.x * o.x + o.y * o.y;
#pragma unroll
            for (int off = 16; off; off >>= 1) {
                s1 += __shfl_xor_sync(0xffffffffu, s1, off);
                s2 += __shfl_xor_sync(0xffffffffu, s2, off);
            }
            float mean = s1 * (1.f / 64.f);
            float var = s2 * (1.f / 64.f) - mean * mean;
            float rstd = rsqrtf(var + LN_EPS);
            float z0 = fmaxf((o.x - mean) * rstd * gv.x + tv.x, 0.f);
            float z1 = fmaxf((o.y - mean) * rstd * gv.y + tv.y, 0.f);
            *reinterpret_cast<float2*>(&zout[(size_t)row * 64 + 2 * lane]) =
                make_float2(z0, z1);
        }
    }
}

// ---------------- GEMM NOUT=128, K=64, K-chunked smem (24 KB), fused LN+ReLU --
// lane owns features {4l..4l+3}. Same chain-spacing reorder as gemm64.
__global__ __launch_bounds__(256, 4) void gemm128_kernel(const float* __restrict__ A,
                                                         const float* __restrict__ W,
                                                         const float* __restrict__ bias,
                                                         const float* __restrict__ lng,
                                                         const float* __restrict__ lnb,
                                                         float* __restrict__ C, int M) {
    constexpr int K = 64, KC = 32;
    __shared__ float sA[64 * KC];   // 8 KB
    __shared__ float sW[KC * 128];  // 16 KB
    const int tid = threadIdx.x;
    const int m0 = blockIdx.x * 64;
    const int warp = tid >> 5, lane = tid & 31;
    const int r0 = warp * 8;

    float2 acc[8][2];
#pragma unroll
    for (int r = 0; r < 8; r++) {
        acc[r][0] = make_float2(0.f, 0.f);
        acc[r][1] = make_float2(0.f, 0.f);
    }

#pragma unroll
    for (int kc = 0; kc < K; kc += KC) {
        if (kc) __syncthreads();
        for (int idx = tid * 4; idx < 64 * KC; idx += 1024) {
            int row = idx / KC, col = idx % KC;
            float4 v = make_float4(0.f, 0.f, 0.f, 0.f);
            if (m0 + row < M)
                v = *reinterpret_cast<const float4*>(&A[(size_t)(m0 + row) * K + kc + col]);
            *reinterpret_cast<float4*>(&sA[idx]) = v;
        }
        for (int idx = tid * 4; idx < KC * 128; idx += 1024) {
            int row = idx / 128, col = idx % 128;
            *reinterpret_cast<float4*>(&sW[idx]) =
                *reinterpret_cast<const float4*>(&W[(kc + row) * 128 + col]);
        }
        __syncthreads();

#pragma unroll 2
        for (int k4 = 0; k4 < KC; k4 += 4) {
            float4 av[8];
#pragma unroll
            for (int r = 0; r < 8; r++)
                av[r] = *reinterpret_cast<const float4*>(&sA[(r0 + r) * KC + k4]);
            float4 wa = *reinterpret_cast<const float4*>(&sW[(k4 + 0) * 128 + 4 * lane]);
            float4 wb = *reinterpret_cast<const float4*>(&sW[(k4 + 1) * 128 + 4 * lane]);
            float4 wc = *reinterpret_cast<const float4*>(&sW[(k4 + 2) * 128 + 4 * lane]);
            float4 wd = *reinterpret_cast<const float4*>(&sW[(k4 + 3) * 128 + 4 * lane]);
            // k-substep outer, rows inner: same-acc updates 16 instrs apart
#pragma unroll
            for (int r = 0; r < 8; r++) {
                acc[r][0] = ffma2(av[r].x, make_float2(wa.x, wa.y), acc[r][0]);
                acc[r][1] = ffma2(av[r].x, make_float2(wa.z, wa.w), acc[r][1]);
            }
#pragma unroll
            for (int r = 0; r < 8; r++) {
                acc[r][0] = ffma2(av[r].y, make_float2(wb.x, wb.y), acc[r][0]);
                acc[r][1] = ffma2(av[r].y, make_float2(wb.z, wb.w), acc[r][1]);
            }
#pragma unroll
            for (int r = 0; r < 8; r++) {
                acc[r][0] = ffma2(av[r].z, make_float2(wc.x, wc.y), acc[r][0]);
                acc[r][1] = ffma2(av[r].z, make_float2(wc.z, wc.w), acc[r][1]);
            }
#pragma unroll
            for (int r = 0; r < 8; r++) {
                acc[r][0] = ffma2(av[r].w, make_float2(wd.x, wd.y), acc[r][0]);
                acc[r][1] = ffma2(av[r].w, make_float2(wd.z, wd.w), acc[r][1]);
            }
        }
    }

    const float4 bv = *reinterpret_cast<const float4*>(&bias[4 * lane]);
    const float4 gv = *reinterpret_cast<const float4*>(&lng[4 * lane]);
    const float4 tv = *reinterpret_cast<const float4*>(&lnb[4 * lane]);
#pragma unroll
    for (int r = 0; r < 8; r++) {
        int row = m0 + r0 + r;
        if (row >= M) break;  // warp-uniform
        float v0 = acc[r][0].x + bv.x, v1 = acc[r][0].y + bv.y;
        float v2 = acc[r][1].x + bv.z, v3 = acc[r][1].y + bv.w;
        float s1 = v0 + v1 + v2 + v3;
        float s2 = v0 * v0 + v1 * v1 + v2 * v2 + v3 * v3;
#pragma unroll
        for (int off = 16; off; off >>= 1) {
            s1 += __shfl_xor_sync(0xffffffffu, s1, off);
            s2 += __shfl_xor_sync(0xffffffffu, s2, off);
        }
        float mean = s1 * (1.f / 128.f);
        float var = s2 * (1.f / 128.f) - mean * mean;
        float rstd = rsqrtf(var + LN_EPS);
        v0 = fmaxf((v0 - mean) * rstd * gv.x + tv.x, 0.f);
        v1 = fmaxf((v1 - mean) * rstd * gv.y + tv.y, 0.f);
        v2 = fmaxf((v2 - mean) * rstd * gv.z + tv.z, 0.f);
        v3 = fmaxf((v3 - mean) * rstd * gv.w + tv.w, 0.f);
        *reinterpret_cast<float4*>(&C[(size_t)row * 128 + 4 * lane]) =
            make_float4(v0, v1, v2, v3);
    }
}

// ---------------- launch ------------------------------------------------------
extern "C" void kernel_launch(void* const* d_in, const int* in_sizes, int n_in,
                              void* d_out, int out_size) {
    const float* x      = (const float*)d_in[0];
    const int*   ei     = (const int*)d_in[1];
    const float* eattr  = (const float*)d_in[2];
    const float* node_W = (const float*)d_in[3];
    const float* node_b = (const float*)d_in[4];
    const float* edge_W = (const float*)d_in[5];
    const float* edge_b = (const float*)d_in[6];
    const float* t      = (const float*)d_in[7];
    const float* mlp1_W = (const float*)d_in[8];
    const float* mlp1_b = (const float*)d_in[9];
    const float* ln_g   = (const float*)d_in[10];
    const float* ln_b   = (const float*)d_in[11];
    const float* mlp2_W = (const float*)d_in[12];
    const float* mlp2_b = (const float*)d_in[13];
    const float* blk_g  = (const float*)d_in[14];
    const float* blk_b  = (const float*)d_in[15];
    float* out = (float*)d_out;

    const int* src = ei;
    const int* dst = ei + EE;

    __half2* p_ea2;
    float *p_h, *p_z, *p_agg, *p_t1;
    int *p_deg, *p_rowptr, *p_cursor, *p_psrc, *p_bsum, *p_boff;
    cudaGetSymbolAddress((void**)&p_ea2, g_ea2);
    cudaGetSymbolAddress((void**)&p_h, g_h);
    cudaGetSymbolAddress((void**)&p_z, g_z);
    cudaGetSymbolAddress((void**)&p_agg, g_agg);
    cudaGetSymbolAddress((void**)&p_t1, g_t1);
    cudaGetSymbolAddress((void**)&p_deg, g_deg);
    cudaGetSymbolAddress((void**)&p_rowptr, g_rowptr);
    cudaGetSymbolAddress((void**)&p_cursor, g_cursor);
    cudaGetSymbolAddress((void**)&p_psrc, g_psrc);
    cudaGetSymbolAddress((void**)&p_bsum, g_bsum);
    cudaGetSymbolAddress((void**)&p_boff, g_boff);

    const int warpBlocks = (NN * 32 + 255) / 256;  // 6250 (one warp per node)
    const int gemmBlocks = (NN + 63) / 64;         // 782

    // --- CSR build (parallel scan) + fused edge encode into permuted fp16 slots
    cudaMemsetAsync(p_deg, 0, NN * sizeof(int));
    hist_kernel<<<(EE + 255) / 256, 256>>>(dst, p_deg);
    chunk_sum_kernel<<<NCHUNK, 256>>>(p_deg, p_bsum);
    chunk_scan_kernel<<<1, 256>>>(p_bsum, p_boff);
    rowptr_kernel<<<NCHUNK, 256>>>(p_deg, p_boff, p_rowptr, p_cursor);
    scatter_enc_kernel<<<4096, 256>>>(src, dst, eattr, edge_W, edge_b,
                                      p_cursor, p_psrc, p_ea2);

    // --- node encoder: h = x @ node_W + node_b ---
    gemm64_kernel<<<gemmBlocks, 256>>>(x, node_W, node_b, nullptr, p_h,
                                       nullptr, nullptr, nullptr, NN);

    // --- layers (next layer's pre-norm z and the final output fused into gemm2)
    for (int i = 0; i < LL; i++) {
        const float* zin = (i == 0) ? p_h : p_z;
        agg_kernel<<<warpBlocks, 256>>>(zin, p_ea2, p_psrc, p_rowptr, t + i, p_agg);
        gemm128_kernel<<<gemmBlocks, 256>>>(
            p_agg, mlp1_W + (size_t)i * 64 * 128, mlp1_b + i * 128,
            ln_g + i * 128, ln_b + i * 128, p_t1, NN);
        const bool last = (i == LL - 1);
        const float* png = last ? blk_g : blk_g + (i + 1) * HH;  // final norm uses blk[0]
        const float* pnb = last ? blk_b : blk_b + (i + 1) * HH;
        float* zo = last ? out : p_z;
        gemm64_kernel<<<gemmBlocks, 256>>>(
            p_t1, mlp2_W + (size_t)i * 128 * 64, mlp2_b + i * 64,
            (i > 0 ? p_h : nullptr), p_h, png, pnb, zo, NN);
    }
}